// round 13
// baseline (speedup 1.0000x reference)
#include <cuda_runtime.h>

#define Bn   16
#define Tn   262144
#define HOP  256
#define WINL 1024
#define PADL 384
#define Fn   1024
#define Pn   22
#define NGRP 512            // frame groups (32 frames each)
#define NSEQ (Bn * Fn)
#define NCHUNK 14           // chunks computed per warp
#define WARM_CHUNKS 8       // 256-sample warm-up for warps 1..3 (verified safe)

// Windowed synthesized frames (64MB scratch; no allocation in kernel_launch)
__device__ float d_frames[(size_t)NSEQ * WINL];

typedef unsigned long long ull;

static __device__ __forceinline__ ull pk2(float lo, float hi) {
    ull r; asm("mov.b64 %0,{%1,%2};" : "=l"(r) : "f"(lo), "f"(hi)); return r;
}
static __device__ __forceinline__ void upk2(float& lo, float& hi, ull v) {
    asm("mov.b64 {%0,%1},%2;" : "=f"(lo), "=f"(hi) : "l"(v));
}
static __device__ __forceinline__ ull fma2_(ull a, ull b, ull c) {
    ull r; asm("fma.rn.f32x2 %0,%1,%2,%3;" : "=l"(r) : "l"(a), "l"(b), "l"(c)); return r;
}
static __device__ __forceinline__ ull mul2_(ull a, ull b) {
    ull r; asm("mul.rn.f32x2 %0,%1,%2;" : "=l"(r) : "l"(a), "l"(b)); return r;
}
static __device__ __forceinline__ ull add2_(ull a, ull b) {
    ull r; asm("add.rn.f32x2 %0,%1,%2;" : "=l"(r) : "l"(a), "l"(b)); return r;
}

static __device__ __forceinline__ float hannf(int t) {
    return 0.5f - 0.5f * __cosf(6.283185307179586f * (float)t * (1.0f / 1024.0f));
}

// ---------------------------------------------------------------------------
// Kernel 1: one CTA (128 threads = 4 warps) per 32-frame group.
//   FULLY DECOUPLED warps (no smem acc, no CTA barriers, no races):
//     warp w: tbase = 192*w, computes 14 chunks = t [192w, 192w+448)
//       warp0 emits chunks 0..13  -> t [0,448)
//       warp1 emits chunks 8..13  -> t [448,640)   (warm-up = 256 samples)
//       warp2 emits chunks 8..13  -> t [640,832)   (warm-up = 256)
//       warp3 emits chunks 8..13  -> t [832,1024)  (warm-up = 256)
//   Emitted samples are windowed and written straight to d_frames (coalesced);
//   kernel 2 gathers the 4-frame OLA sum per output sample.
// ---------------------------------------------------------------------------
__global__ void __launch_bounds__(128)
lpc_kernel(const float* __restrict__ ex,
           const float* __restrict__ gain,
           const float* __restrict__ a) {
    __shared__ float bufs[4][32 * 34];   // per-warp: x stage AND y tile (in place)

    const int warp = threadIdx.x >> 5;        // segment 0..3
    const int lane = threadIdx.x & 31;
    const int gw   = blockIdx.x;               // frame group 0..511
    const int s0   = gw * 32;
    const int s    = s0 + lane;                 // this lane's sequence
    const int b    = s >> 10;
    const int f0   = (gw & 31) * 32;            // base frame within batch

    float* __restrict__ buf = bufs[warp];

    const float g = gain[s];

    // c[q] = -a[q-1] (q=1..22), c[23]=c[24]=0
    float c[25];
    #pragma unroll
    for (int p = 0; p < Pn; ++p) c[p + 1] = -a[s * Pn + p];
    c[23] = 0.0f; c[24] = 0.0f;
    const float c1 = c[1];

    // CA[k] = (c_{2k+1}, c_{2k+2}) : y0 dot
    // CE[k] = (c_{2k+2}, c_{2k+3}) : y1 shifted dot (y1 = c1*y0 + g*x1 + dotE)
    ull CA[11], CE[11], H[11];
    #pragma unroll
    for (int k = 0; k < 11; ++k) {
        CA[k] = pk2(c[2 * k + 1], c[2 * k + 2]);
        CE[k] = pk2(c[2 * k + 2], c[2 * k + 3]);
        H[k]  = 0ull;
    }

    const float* __restrict__ exb = ex + b * Tn;
    const int tbase      = 192 * warp;
    const int emit_start = warp ? WARM_CHUNKS : 0;

    // prefetch chunk 0 (coalesced: lane sweeps time, r sweeps frames)
    float xr[32];
    #pragma unroll
    for (int r = 0; r < 32; ++r) {
        int idx = (f0 + r) * HOP + tbase + lane - PADL;
        xr[r] = ((unsigned)idx < (unsigned)Tn) ? exb[idx] : 0.0f;
    }

    for (int cc = 0; cc < NCHUNK; ++cc) {
        const int t0 = tbase + 32 * cc;

        // commit prefetched chunk to this warp's buffer [seq row][time col]
        #pragma unroll
        for (int r = 0; r < 32; ++r) buf[r * 34 + lane] = xr[r];
        __syncwarp();

        // prefetch next chunk; latency hides under recurrence
        if (cc < NCHUNK - 1) {
            const int t1 = t0 + 32;
            #pragma unroll
            for (int r = 0; r < 32; ++r) {
                int idx = (f0 + r) * HOP + t1 + lane - PADL;
                xr[r] = ((unsigned)idx < (unsigned)Tn) ? exb[idx] : 0.0f;
            }
        }

        // 16 blocks x 2 samples; buf row consumed and overwritten in place
        float* xrow = buf + lane * 34;
        float2 xp2 = *(const float2*)xrow;
        #pragma unroll
        for (int bk = 0; bk < 16; ++bk) {
            float2 xn2;
            if (bk < 15) xn2 = *(const float2*)(xrow + 2 * bk + 2);
            const float x0 = xp2.x, x1 = xp2.y;

            // even/odd split packed dots, H[0] last
            ull ae = mul2_(CA[10], H[10]);
            ae = fma2_(CA[8], H[8], ae);
            ae = fma2_(CA[6], H[6], ae);
            ae = fma2_(CA[4], H[4], ae);
            ae = fma2_(CA[2], H[2], ae);
            ull ao = mul2_(CA[9], H[9]);
            ao = fma2_(CA[7], H[7], ao);
            ao = fma2_(CA[5], H[5], ao);
            ao = fma2_(CA[3], H[3], ao);
            ao = fma2_(CA[1], H[1], ao);
            ae = fma2_(CA[0], H[0], ae);
            const ull accA = add2_(ae, ao);

            ull ee = mul2_(CE[10], H[10]);
            ee = fma2_(CE[8], H[8], ee);
            ee = fma2_(CE[6], H[6], ee);
            ee = fma2_(CE[4], H[4], ee);
            ee = fma2_(CE[2], H[2], ee);
            ull eo = mul2_(CE[9], H[9]);
            eo = fma2_(CE[7], H[7], eo);
            eo = fma2_(CE[5], H[5], eo);
            eo = fma2_(CE[3], H[3], eo);
            eo = fma2_(CE[1], H[1], eo);
            ee = fma2_(CE[0], H[0], ee);
            const ull accE = add2_(ee, eo);

            float aLo, aHi, eLo, eHi;
            upk2(aLo, aHi, accA);
            upk2(eLo, eHi, accE);
            const float y0 = fmaf(g, x0, aLo + aHi);
            const float y1 = fmaf(c1, y0, fmaf(g, x1, eLo + eHi));

            *(float2*)(xrow + 2 * bk) = make_float2(y0, y1);

            #pragma unroll
            for (int k = 10; k > 0; --k) H[k] = H[k - 1];
            H[0] = pk2(y1, y0);

            xp2 = xn2;
        }
        __syncwarp();

        // windowed frame write (emit range only), fully coalesced
        if (cc >= emit_start) {
            const float wv = hannf(t0 + lane);
            float* __restrict__ fout = d_frames + (size_t)s0 * WINL + t0 + lane;
            #pragma unroll
            for (int r = 0; r < 32; ++r)
                fout[(size_t)r * WINL] = buf[r * 34 + lane] * wv;
        }
        __syncwarp();
    }
}

// ---------------------------------------------------------------------------
// Kernel 2: gather-OLA (verified in R3). Each output sample = sum of exactly
//   <=4 frame samples. Interior norm is exactly 2 (4-phase periodic Hann);
//   edges use the hann function. float4 everywhere (4 | HOP).
// ---------------------------------------------------------------------------
__global__ void final_kernel(float* __restrict__ out) {
    const int i = blockIdx.x * blockDim.x + threadIdx.x;   // float4 group id
    if (i >= Bn * Tn / 4) return;
    const int b   = i >> 16;                // Tn/4 = 65536 groups per batch
    const int n0  = (i & 65535) << 2;
    const int pos = n0 + PADL;
    const int fhi = pos >> 8;               // HOP = 256; constant across group

    const float* __restrict__ fb = d_frames + (size_t)b * Fn * WINL;
    float4 acc = make_float4(0.f, 0.f, 0.f, 0.f);
    #pragma unroll
    for (int k = 0; k < 4; ++k) {
        const int ff = fhi - k;
        if (ff >= 0 && ff < Fn) {
            const float4 v = *(const float4*)(fb + (size_t)ff * WINL + (pos - ff * HOP));
            acc.x += v.x; acc.y += v.y; acc.z += v.z; acc.w += v.w;
        }
    }

    float4 o;
    if (pos >= 3 * HOP && fhi <= Fn - 1) {           // interior: norm == 2
        o.x = acc.x * 0.5f; o.y = acc.y * 0.5f;
        o.z = acc.z * 0.5f; o.w = acc.w * 0.5f;
    } else {                                         // 2x384 samples per batch
        float nrm[4] = {0.f, 0.f, 0.f, 0.f};
        #pragma unroll
        for (int j = 0; j < 4; ++j) {
            #pragma unroll
            for (int k = 0; k < 4; ++k) {
                const int ff = fhi - k;
                if (ff >= 0 && ff < Fn) nrm[j] += hannf(pos + j - ff * HOP);
            }
        }
        o.x = acc.x / nrm[0]; o.y = acc.y / nrm[1];
        o.z = acc.z / nrm[2]; o.w = acc.w / nrm[3];
    }
    ((float4*)out)[i] = o;
}

// ---------------------------------------------------------------------------
extern "C" void kernel_launch(void* const* d_in, const int* in_sizes, int n_in,
                              void* d_out, int out_size) {
    const float* ex   = (const float*)d_in[0];
    const float* gain = (const float*)d_in[1];
    const float* a    = (const float*)d_in[2];
    float* out = (float*)d_out;

    lpc_kernel<<<NGRP, 128>>>(ex, gain, a);
    final_kernel<<<(Bn * Tn / 4 + 255) / 256, 256>>>(out);
}

// round 14
// speedup vs baseline: 1.1470x; 1.1470x over previous
#include <cuda_runtime.h>

#define Bn   16
#define Tn   262144
#define HOP  256
#define WINL 1024
#define PADL 384
#define Fn   1024
#define Pn   22
#define NGRP 512            // frame groups (32 frames each); 1 warp per group
#define SPAN 8960           // per-group OLA span
#define STRIPL 768          // seam width
#define NCHUNK 32           // full sequence per warp: zero redundancy

// Cross-group seam partial sums
__device__ float d_strip_lo[NGRP][STRIPL];
__device__ float d_strip_hi[NGRP][STRIPL];

typedef unsigned long long ull;

static __device__ __forceinline__ ull pk2(float lo, float hi) {
    ull r; asm("mov.b64 %0,{%1,%2};" : "=l"(r) : "f"(lo), "f"(hi)); return r;
}
static __device__ __forceinline__ void upk2(float& lo, float& hi, ull v) {
    asm("mov.b64 {%0,%1},%2;" : "=f"(lo), "=f"(hi) : "l"(v));
}
static __device__ __forceinline__ ull fma2_(ull a, ull b, ull c) {
    ull r; asm("fma.rn.f32x2 %0,%1,%2,%3;" : "=l"(r) : "l"(a), "l"(b), "l"(c)); return r;
}
static __device__ __forceinline__ ull mul2_(ull a, ull b) {
    ull r; asm("mul.rn.f32x2 %0,%1,%2;" : "=l"(r) : "l"(a), "l"(b)); return r;
}
static __device__ __forceinline__ ull add2_(ull a, ull b) {
    ull r; asm("add.rn.f32x2 %0,%1,%2;" : "=l"(r) : "l"(a), "l"(b)); return r;
}

static __device__ __forceinline__ float hannf(int t) {
    return 0.5f - 0.5f * __cosf(6.283185307179586f * (float)t * (1.0f / 1024.0f));
}

// smem (floats): acc[SPAN] | buf[32*34]   (buf = x stage AND y tile, in place)
#define BUF_F (32 * 34)
#define SMEM_FLOATS (SPAN + BUF_F)
#define SMEM_BYTES  (SMEM_FLOATS * 4)   // 40448 B; 32-thread CTA

// ---------------------------------------------------------------------------
// Kernel 1: ONE WARP per 32-frame group (512 CTAs x 32 threads).
//   Zero redundancy: each lane runs its full 1024-sample sequence serially.
//   Empirical law (R3/R6/R12): lpc wall  ~ total warp-chunks (fma-pipe
//   saturated by single-warp ILP), so minimum work = minimum time.
//   The single warp owns the group's whole OLA accumulator -> race-free with
//   no CTA barriers by construction. Interior written directly (norm == 2);
//   768-sample seams go to strip buffers.
// ---------------------------------------------------------------------------
__global__ void __launch_bounds__(32)
lpc_ola_kernel(const float* __restrict__ ex,
               const float* __restrict__ gain,
               const float* __restrict__ a,
               float* __restrict__ out) {
    extern __shared__ float smem[];

    const int lane = threadIdx.x & 31;
    const int gw   = blockIdx.x;               // frame group 0..511
    const int s0   = gw * 32;
    const int s    = s0 + lane;                 // this lane's sequence
    const int b    = s >> 10;
    const int ww   = gw & 31;                   // group index within batch
    const int f0   = ww * 32;                   // base frame

    float* __restrict__ acc = smem;
    float* __restrict__ buf = smem + SPAN;

    // zero shared accumulator
    #pragma unroll 4
    for (int i = lane; i < SPAN / 4; i += 32)
        ((float4*)acc)[i] = make_float4(0.f, 0.f, 0.f, 0.f);

    const float g = gain[s];

    // c[q] = -a[q-1] (q=1..22), c[23]=c[24]=0
    float c[25];
    #pragma unroll
    for (int p = 0; p < Pn; ++p) c[p + 1] = -a[s * Pn + p];
    c[23] = 0.0f; c[24] = 0.0f;
    const float c1 = c[1];

    // CA[k] = (c_{2k+1}, c_{2k+2}) : y0 dot
    // CE[k] = (c_{2k+2}, c_{2k+3}) : y1 shifted dot (y1 = c1*y0 + g*x1 + dotE)
    ull CA[11], CE[11], H[11];
    #pragma unroll
    for (int k = 0; k < 11; ++k) {
        CA[k] = pk2(c[2 * k + 1], c[2 * k + 2]);
        CE[k] = pk2(c[2 * k + 2], c[2 * k + 3]);
        H[k]  = 0ull;
    }

    const float* __restrict__ exb = ex + b * Tn;

    // prefetch chunk 0 (coalesced: lane sweeps time, r sweeps frames)
    float xr[32];
    #pragma unroll
    for (int r = 0; r < 32; ++r) {
        int idx = (f0 + r) * HOP + lane - PADL;
        xr[r] = ((unsigned)idx < (unsigned)Tn) ? exb[idx] : 0.0f;
    }

    for (int cc = 0; cc < NCHUNK; ++cc) {
        const int t0 = 32 * cc;

        // commit prefetched chunk to the buffer [seq row][time col]
        #pragma unroll
        for (int r = 0; r < 32; ++r) buf[r * 34 + lane] = xr[r];
        __syncwarp();

        // prefetch next chunk; latency hides under recurrence
        if (cc < NCHUNK - 1) {
            const int t1 = t0 + 32;
            #pragma unroll
            for (int r = 0; r < 32; ++r) {
                int idx = (f0 + r) * HOP + t1 + lane - PADL;
                xr[r] = ((unsigned)idx < (unsigned)Tn) ? exb[idx] : 0.0f;
            }
        }

        // 16 blocks x 2 samples; buf row consumed and overwritten in place
        float* xrow = buf + lane * 34;
        float2 xp2 = *(const float2*)xrow;
        #pragma unroll
        for (int bk = 0; bk < 16; ++bk) {
            float2 xn2;
            if (bk < 15) xn2 = *(const float2*)(xrow + 2 * bk + 2);
            const float x0 = xp2.x, x1 = xp2.y;

            // even/odd split packed dots, H[0] last
            ull ae = mul2_(CA[10], H[10]);
            ae = fma2_(CA[8], H[8], ae);
            ae = fma2_(CA[6], H[6], ae);
            ae = fma2_(CA[4], H[4], ae);
            ae = fma2_(CA[2], H[2], ae);
            ull ao = mul2_(CA[9], H[9]);
            ao = fma2_(CA[7], H[7], ao);
            ao = fma2_(CA[5], H[5], ao);
            ao = fma2_(CA[3], H[3], ao);
            ao = fma2_(CA[1], H[1], ao);
            ae = fma2_(CA[0], H[0], ae);
            const ull accA = add2_(ae, ao);

            ull ee = mul2_(CE[10], H[10]);
            ee = fma2_(CE[8], H[8], ee);
            ee = fma2_(CE[6], H[6], ee);
            ee = fma2_(CE[4], H[4], ee);
            ee = fma2_(CE[2], H[2], ee);
            ull eo = mul2_(CE[9], H[9]);
            eo = fma2_(CE[7], H[7], eo);
            eo = fma2_(CE[5], H[5], eo);
            eo = fma2_(CE[3], H[3], eo);
            eo = fma2_(CE[1], H[1], eo);
            ee = fma2_(CE[0], H[0], ee);
            const ull accE = add2_(ee, eo);

            float aLo, aHi, eLo, eHi;
            upk2(aLo, aHi, accA);
            upk2(eLo, eHi, accE);
            const float y0 = fmaf(g, x0, aLo + aHi);
            const float y1 = fmaf(c1, y0, fmaf(g, x1, eLo + eHi));

            *(float2*)(xrow + 2 * bk) = make_float2(y0, y1);

            #pragma unroll
            for (int k = 10; k > 0; --k) H[k] = H[k - 1];
            H[0] = pk2(y1, y0);

            xp2 = xn2;
        }
        __syncwarp();

        // windowed OLA accumulate — single warp owns acc, lanes write
        // distinct cells: race-free with no barriers
        const float wv = hannf(t0 + lane);
        #pragma unroll
        for (int r = 0; r < 32; ++r)
            acc[r * HOP + t0 + lane] += buf[r * 34 + lane] * wv;
        __syncwarp();
    }

    // interior [768, 8192): all 4 contributions local; norm == 2 exactly
    float* __restrict__ outb = out + (size_t)b * Tn + ww * 8192 + 384;
    const float4* __restrict__ acc4 = (const float4*)(acc + STRIPL);
    #pragma unroll 4
    for (int i = lane; i < (8192 - STRIPL) / 4; i += 32) {
        float4 v = acc4[i];
        v.x *= 0.5f; v.y *= 0.5f; v.z *= 0.5f; v.w *= 0.5f;
        ((float4*)outb)[i] = v;
    }
    // seams for kernel 2
    #pragma unroll
    for (int j = lane; j < STRIPL; j += 32) {
        d_strip_lo[gw][j] = acc[j];
        d_strip_hi[gw][j] = acc[8192 + j];
    }
}

// ---------------------------------------------------------------------------
// Kernel 2: resolve seams. One block per region, 192 threads, float4/thread.
//   Non-edge seams have norm == 2 exactly; batch edges use hann norms.
// ---------------------------------------------------------------------------
__global__ void __launch_bounds__(192)
strip_kernel(float* __restrict__ out) {
    const int rg = blockIdx.x;
    const int q  = threadIdx.x;        // float4 index 0..191

    if (rg < NGRP) {
        const int w  = rg;
        const int ww = w & 31;
        const int bI = w >> 5;
        const int pbase = ww * 8192;
        const float4 lo4 = ((const float4*)d_strip_lo[w])[q];
        if (ww > 0) {                  // interior seam: norm exactly 2
            const float4 hi4 = ((const float4*)d_strip_hi[w - 1])[q];
            float4 v;
            v.x = (lo4.x + hi4.x) * 0.5f;
            v.y = (lo4.y + hi4.y) * 0.5f;
            v.z = (lo4.z + hi4.z) * 0.5f;
            v.w = (lo4.w + hi4.w) * 0.5f;
            *(float4*)(out + (size_t)bI * Tn + pbase + 4 * q - PADL) = v;
            return;
        }
        // batch-leading edge: per element with window norms
        const float sv[4] = {lo4.x, lo4.y, lo4.z, lo4.w};
        #pragma unroll
        for (int e = 0; e < 4; ++e) {
            const int p = pbase + 4 * q + e;
            const int o = p - PADL;
            if ((unsigned)o >= (unsigned)Tn) continue;
            const int fhi = p >> 8;
            float norm = 0.0f;
            #pragma unroll
            for (int k = 0; k < 4; ++k) {
                const int ff = fhi - k;
                if (ff >= 0 && ff < Fn) norm += hannf(p - ff * HOP);
            }
            out[(size_t)bI * Tn + o] = sv[e] / norm;
        }
    } else {
        const int w = ((rg - NGRP) << 5) | 31;   // batch-trailing edge
        const int bI = w >> 5;
        const int pbase = 32 * 8192;
        const float4 hi4 = ((const float4*)d_strip_hi[w])[q];
        const float sv[4] = {hi4.x, hi4.y, hi4.z, hi4.w};
        #pragma unroll
        for (int e = 0; e < 4; ++e) {
            const int p = pbase + 4 * q + e;
            const int o = p - PADL;
            if ((unsigned)o >= (unsigned)Tn) continue;
            const int fhi = p >> 8;
            float norm = 0.0f;
            #pragma unroll
            for (int k = 0; k < 4; ++k) {
                const int ff = fhi - k;
                if (ff >= 0 && ff < Fn) norm += hannf(p - ff * HOP);
            }
            out[(size_t)bI * Tn + o] = sv[e] / norm;
        }
    }
}

// ---------------------------------------------------------------------------
extern "C" void kernel_launch(void* const* d_in, const int* in_sizes, int n_in,
                              void* d_out, int out_size) {
    const float* ex   = (const float*)d_in[0];
    const float* gain = (const float*)d_in[1];
    const float* a    = (const float*)d_in[2];
    float* out = (float*)d_out;

    cudaFuncSetAttribute(lpc_ola_kernel,
                         cudaFuncAttributeMaxDynamicSharedMemorySize, SMEM_BYTES);
    lpc_ola_kernel<<<NGRP, 32, SMEM_BYTES>>>(ex, gain, a, out);
    strip_kernel<<<NGRP + Bn, 192>>>(out);
}

// round 15
// speedup vs baseline: 1.2037x; 1.0495x over previous
#include <cuda_runtime.h>

#define Bn   16
#define Tn   262144
#define HOP  256
#define WINL 1024
#define PADL 384
#define Fn   1024
#define Pn   22
#define NGRP 512            // frame groups (32 frames each); 1 warp per group
#define SPAN 8960           // per-group OLA span
#define STRIPL 768          // seam width
#define NCHUNK 32           // full sequence per warp: zero redundancy

// Cross-group seam partial sums
__device__ float d_strip_lo[NGRP][STRIPL];
__device__ float d_strip_hi[NGRP][STRIPL];

typedef unsigned long long ull;

static __device__ __forceinline__ ull pk2(float lo, float hi) {
    ull r; asm("mov.b64 %0,{%1,%2};" : "=l"(r) : "f"(lo), "f"(hi)); return r;
}
static __device__ __forceinline__ void upk2(float& lo, float& hi, ull v) {
    asm("mov.b64 {%0,%1},%2;" : "=f"(lo), "=f"(hi) : "l"(v));
}
static __device__ __forceinline__ ull fma2_(ull a, ull b, ull c) {
    ull r; asm("fma.rn.f32x2 %0,%1,%2,%3;" : "=l"(r) : "l"(a), "l"(b), "l"(c)); return r;
}
static __device__ __forceinline__ ull mul2_(ull a, ull b) {
    ull r; asm("mul.rn.f32x2 %0,%1,%2;" : "=l"(r) : "l"(a), "l"(b)); return r;
}
static __device__ __forceinline__ ull add2_(ull a, ull b) {
    ull r; asm("add.rn.f32x2 %0,%1,%2;" : "=l"(r) : "l"(a), "l"(b)); return r;
}

static __device__ __forceinline__ float hannf(int t) {
    return 0.5f - 0.5f * __cosf(6.283185307179586f * (float)t * (1.0f / 1024.0f));
}

// smem (floats): acc[4 warps][SPAN] | buf[4 warps][32*34]
#define BUF_F (32 * 34)
#define SMEM_FLOATS (4 * SPAN + 4 * BUF_F)
#define SMEM_BYTES  (SMEM_FLOATS * 4)   // 160768 B -> 1 CTA/SM

// ---------------------------------------------------------------------------
// Kernel 1: 128 CTAs x 128 threads; warp w handles frame group 4*blk+w.
//   ZERO redundancy (each lane runs its full 1024-sample sequence serially),
//   perfect SMSP spread (4-warp CTAs -> 1 warp per SMSP; R14 showed 1-warp
//   CTAs pile onto one SMSP), per-warp smem OLA accumulator (sole owner ->
//   race-free, no barriers at all).
// ---------------------------------------------------------------------------
__global__ void __launch_bounds__(128, 1)
lpc_ola_kernel(const float* __restrict__ ex,
               const float* __restrict__ gain,
               const float* __restrict__ a,
               float* __restrict__ out) {
    extern __shared__ float smem[];

    const int warp = threadIdx.x >> 5;
    const int lane = threadIdx.x & 31;
    const int gw   = blockIdx.x * 4 + warp;    // frame group 0..511
    const int s0   = gw * 32;
    const int s    = s0 + lane;                 // this lane's sequence
    const int b    = s >> 10;
    const int ww   = gw & 31;                   // group index within batch
    const int f0   = ww * 32;                   // base frame

    float* __restrict__ acc = smem + warp * SPAN;
    float* __restrict__ buf = smem + 4 * SPAN + warp * BUF_F;

    // zero this warp's accumulator
    #pragma unroll 4
    for (int i = lane; i < SPAN / 4; i += 32)
        ((float4*)acc)[i] = make_float4(0.f, 0.f, 0.f, 0.f);

    const float g = gain[s];

    // c[q] = -a[q-1] (q=1..22), c[23]=c[24]=0
    float c[25];
    #pragma unroll
    for (int p = 0; p < Pn; ++p) c[p + 1] = -a[s * Pn + p];
    c[23] = 0.0f; c[24] = 0.0f;
    const float c1 = c[1];

    // CA[k] = (c_{2k+1}, c_{2k+2}) : y0 dot
    // CE[k] = (c_{2k+2}, c_{2k+3}) : y1 shifted dot (y1 = c1*y0 + g*x1 + dotE)
    ull CA[11], CE[11], H[11];
    #pragma unroll
    for (int k = 0; k < 11; ++k) {
        CA[k] = pk2(c[2 * k + 1], c[2 * k + 2]);
        CE[k] = pk2(c[2 * k + 2], c[2 * k + 3]);
        H[k]  = 0ull;
    }

    const float* __restrict__ exb = ex + b * Tn;

    // prefetch chunk 0 (coalesced: lane sweeps time, r sweeps frames)
    float xr[32];
    #pragma unroll
    for (int r = 0; r < 32; ++r) {
        int idx = (f0 + r) * HOP + lane - PADL;
        xr[r] = ((unsigned)idx < (unsigned)Tn) ? exb[idx] : 0.0f;
    }

    for (int cc = 0; cc < NCHUNK; ++cc) {
        const int t0 = 32 * cc;

        // commit prefetched chunk to the buffer [seq row][time col]
        #pragma unroll
        for (int r = 0; r < 32; ++r) buf[r * 34 + lane] = xr[r];
        __syncwarp();

        // prefetch next chunk; latency hides under recurrence
        if (cc < NCHUNK - 1) {
            const int t1 = t0 + 32;
            #pragma unroll
            for (int r = 0; r < 32; ++r) {
                int idx = (f0 + r) * HOP + t1 + lane - PADL;
                xr[r] = ((unsigned)idx < (unsigned)Tn) ? exb[idx] : 0.0f;
            }
        }

        // 16 blocks x 2 samples; buf row consumed and overwritten in place
        float* xrow = buf + lane * 34;
        float2 xp2 = *(const float2*)xrow;
        #pragma unroll
        for (int bk = 0; bk < 16; ++bk) {
            float2 xn2;
            if (bk < 15) xn2 = *(const float2*)(xrow + 2 * bk + 2);
            const float x0 = xp2.x, x1 = xp2.y;

            // even/odd split packed dots, H[0] last
            ull ae = mul2_(CA[10], H[10]);
            ae = fma2_(CA[8], H[8], ae);
            ae = fma2_(CA[6], H[6], ae);
            ae = fma2_(CA[4], H[4], ae);
            ae = fma2_(CA[2], H[2], ae);
            ull ao = mul2_(CA[9], H[9]);
            ao = fma2_(CA[7], H[7], ao);
            ao = fma2_(CA[5], H[5], ao);
            ao = fma2_(CA[3], H[3], ao);
            ao = fma2_(CA[1], H[1], ao);
            ae = fma2_(CA[0], H[0], ae);
            const ull accA = add2_(ae, ao);

            ull ee = mul2_(CE[10], H[10]);
            ee = fma2_(CE[8], H[8], ee);
            ee = fma2_(CE[6], H[6], ee);
            ee = fma2_(CE[4], H[4], ee);
            ee = fma2_(CE[2], H[2], ee);
            ull eo = mul2_(CE[9], H[9]);
            eo = fma2_(CE[7], H[7], eo);
            eo = fma2_(CE[5], H[5], eo);
            eo = fma2_(CE[3], H[3], eo);
            eo = fma2_(CE[1], H[1], eo);
            ee = fma2_(CE[0], H[0], ee);
            const ull accE = add2_(ee, eo);

            float aLo, aHi, eLo, eHi;
            upk2(aLo, aHi, accA);
            upk2(eLo, eHi, accE);
            const float y0 = fmaf(g, x0, aLo + aHi);
            const float y1 = fmaf(c1, y0, fmaf(g, x1, eLo + eHi));

            *(float2*)(xrow + 2 * bk) = make_float2(y0, y1);

            #pragma unroll
            for (int k = 10; k > 0; --k) H[k] = H[k - 1];
            H[0] = pk2(y1, y0);

            xp2 = xn2;
        }
        __syncwarp();

        // windowed OLA accumulate — this warp solely owns acc: race-free
        const float wv = hannf(t0 + lane);
        #pragma unroll
        for (int r = 0; r < 32; ++r)
            acc[r * HOP + t0 + lane] += buf[r * 34 + lane] * wv;
        __syncwarp();
    }

    // interior [768, 8192): all 4 contributions local; norm == 2 exactly
    float* __restrict__ outb = out + (size_t)b * Tn + ww * 8192 + 384;
    const float4* __restrict__ acc4 = (const float4*)(acc + STRIPL);
    #pragma unroll 4
    for (int i = lane; i < (8192 - STRIPL) / 4; i += 32) {
        float4 v = acc4[i];
        v.x *= 0.5f; v.y *= 0.5f; v.z *= 0.5f; v.w *= 0.5f;
        ((float4*)outb)[i] = v;
    }
    // seams for kernel 2
    #pragma unroll
    for (int j = lane; j < STRIPL; j += 32) {
        d_strip_lo[gw][j] = acc[j];
        d_strip_hi[gw][j] = acc[8192 + j];
    }
}

// ---------------------------------------------------------------------------
// Kernel 2: resolve seams. One block per region, 192 threads, float4/thread.
//   Non-edge seams have norm == 2 exactly; batch edges use hann norms.
// ---------------------------------------------------------------------------
__global__ void __launch_bounds__(192)
strip_kernel(float* __restrict__ out) {
    const int rg = blockIdx.x;
    const int q  = threadIdx.x;        // float4 index 0..191

    if (rg < NGRP) {
        const int w  = rg;
        const int ww = w & 31;
        const int bI = w >> 5;
        const int pbase = ww * 8192;
        const float4 lo4 = ((const float4*)d_strip_lo[w])[q];
        if (ww > 0) {                  // interior seam: norm exactly 2
            const float4 hi4 = ((const float4*)d_strip_hi[w - 1])[q];
            float4 v;
            v.x = (lo4.x + hi4.x) * 0.5f;
            v.y = (lo4.y + hi4.y) * 0.5f;
            v.z = (lo4.z + hi4.z) * 0.5f;
            v.w = (lo4.w + hi4.w) * 0.5f;
            *(float4*)(out + (size_t)bI * Tn + pbase + 4 * q - PADL) = v;
            return;
        }
        // batch-leading edge: per element with window norms
        const float sv[4] = {lo4.x, lo4.y, lo4.z, lo4.w};
        #pragma unroll
        for (int e = 0; e < 4; ++e) {
            const int p = pbase + 4 * q + e;
            const int o = p - PADL;
            if ((unsigned)o >= (unsigned)Tn) continue;
            const int fhi = p >> 8;
            float norm = 0.0f;
            #pragma unroll
            for (int k = 0; k < 4; ++k) {
                const int ff = fhi - k;
                if (ff >= 0 && ff < Fn) norm += hannf(p - ff * HOP);
            }
            out[(size_t)bI * Tn + o] = sv[e] / norm;
        }
    } else {
        const int w = ((rg - NGRP) << 5) | 31;   // batch-trailing edge
        const int bI = w >> 5;
        const int pbase = 32 * 8192;
        const float4 hi4 = ((const float4*)d_strip_hi[w])[q];
        const float sv[4] = {hi4.x, hi4.y, hi4.z, hi4.w};
        #pragma unroll
        for (int e = 0; e < 4; ++e) {
            const int p = pbase + 4 * q + e;
            const int o = p - PADL;
            if ((unsigned)o >= (unsigned)Tn) continue;
            const int fhi = p >> 8;
            float norm = 0.0f;
            #pragma unroll
            for (int k = 0; k < 4; ++k) {
                const int ff = fhi - k;
                if (ff >= 0 && ff < Fn) norm += hannf(p - ff * HOP);
            }
            out[(size_t)bI * Tn + o] = sv[e] / norm;
        }
    }
}

// ---------------------------------------------------------------------------
extern "C" void kernel_launch(void* const* d_in, const int* in_sizes, int n_in,
                              void* d_out, int out_size) {
    const float* ex   = (const float*)d_in[0];
    const float* gain = (const float*)d_in[1];
    const float* a    = (const float*)d_in[2];
    float* out = (float*)d_out;

    cudaFuncSetAttribute(lpc_ola_kernel,
                         cudaFuncAttributeMaxDynamicSharedMemorySize, SMEM_BYTES);
    lpc_ola_kernel<<<128, 128, SMEM_BYTES>>>(ex, gain, a, out);
    strip_kernel<<<NGRP + Bn, 192>>>(out);
}